// round 1
// baseline (speedup 1.0000x reference)
#include <cuda_runtime.h>

// Scratch: qkv [3][8192][768], scores [4][2048][2048]
__device__ float g_qkv[3ull * 8192 * 768];
__device__ float g_s[4ull * 2048 * 2048];

#define BM 128
#define BN 128
#define BK 8
#define TM 8
#define TN 8

// C = alpha * A * op(B), batched via blockIdx.z with byte-element strides.
// TRANSB=false: B is [K,N] row-major. TRANSB=true: B is [N,K] row-major (C = A*B^T).
// All dims assumed multiples of the tile sizes (true for this problem).
template <bool TRANSB>
__global__ __launch_bounds__(256) void gemm_kernel(
    const float* __restrict__ A, const float* __restrict__ B, float* __restrict__ C,
    int M, int N, int K, int lda, int ldb, int ldc,
    long sA, long sB, long sC, float alpha)
{
    A += (long)blockIdx.z * sA;
    B += (long)blockIdx.z * sB;
    C += (long)blockIdx.z * sC;

    __shared__ float As[BK][BM];
    __shared__ float Bs[BK][BN + 4];

    const int tid = threadIdx.x;
    const int tx = tid & 15;        // 16 thread-cols
    const int ty = tid >> 4;        // 16 thread-rows
    const int bm = blockIdx.y * BM;
    const int bn = blockIdx.x * BN;

    float acc[TM][TN];
#pragma unroll
    for (int i = 0; i < TM; i++)
#pragma unroll
        for (int j = 0; j < TN; j++) acc[i][j] = 0.0f;

    for (int k0 = 0; k0 < K; k0 += BK) {
        // Load A tile (BM x BK) -> As[kk][m]
#pragma unroll
        for (int r = 0; r < 4; r++) {
            int i = tid + r * 256;
            int m = i >> 3, kk = i & 7;
            As[kk][m] = A[(long)(bm + m) * lda + (k0 + kk)];
        }
        // Load B tile -> Bs[kk][n]
        if (!TRANSB) {
#pragma unroll
            for (int r = 0; r < 4; r++) {
                int i = tid + r * 256;
                int kk = i >> 7, n = i & 127;
                Bs[kk][n] = B[(long)(k0 + kk) * ldb + (bn + n)];
            }
        } else {
#pragma unroll
            for (int r = 0; r < 4; r++) {
                int i = tid + r * 256;
                int n = i >> 3, kk = i & 7;
                Bs[kk][n] = B[(long)(bn + n) * ldb + (k0 + kk)];
            }
        }
        __syncthreads();

#pragma unroll
        for (int kk = 0; kk < BK; kk++) {
            float a[TM], b[TN];
#pragma unroll
            for (int i = 0; i < TM; i++) a[i] = As[kk][ty * TM + i];
#pragma unroll
            for (int j = 0; j < TN; j++) b[j] = Bs[kk][tx * TN + j];
#pragma unroll
            for (int i = 0; i < TM; i++)
#pragma unroll
                for (int j = 0; j < TN; j++)
                    acc[i][j] = fmaf(a[i], b[j], acc[i][j]);
        }
        __syncthreads();
    }

#pragma unroll
    for (int i = 0; i < TM; i++) {
        long row = bm + ty * TM + i;
#pragma unroll
        for (int j = 0; j < TN; j += 4) {
            float4 v;
            v.x = alpha * acc[i][j + 0];
            v.y = alpha * acc[i][j + 1];
            v.z = alpha * acc[i][j + 2];
            v.w = alpha * acc[i][j + 3];
            *reinterpret_cast<float4*>(&C[row * ldc + bn + tx * TN + j]) = v;
        }
    }
}

// Row softmax over rows of length 2048, in place. One block (256 threads) per row.
__global__ __launch_bounds__(256) void softmax_kernel(float* __restrict__ S)
{
    long row = blockIdx.x;
    float* p = S + row * 2048;
    const int tid = threadIdx.x;

    float local[8];
    float m = -1e30f;
#pragma unroll
    for (int r = 0; r < 8; r++) {
        local[r] = p[tid + r * 256];
        m = fmaxf(m, local[r]);
    }

    __shared__ float red[32];
#pragma unroll
    for (int o = 16; o; o >>= 1) m = fmaxf(m, __shfl_xor_sync(0xffffffffu, m, o));
    if ((tid & 31) == 0) red[tid >> 5] = m;
    __syncthreads();
    if (tid < 32) {
        float v = (tid < 8) ? red[tid] : -1e30f;
#pragma unroll
        for (int o = 4; o; o >>= 1) v = fmaxf(v, __shfl_xor_sync(0xffffffffu, v, o));
        red[tid] = v;
    }
    __syncthreads();
    m = red[0];

    float s = 0.0f;
#pragma unroll
    for (int r = 0; r < 8; r++) {
        local[r] = __expf(local[r] - m);
        s += local[r];
    }
    __shared__ float red2[32];
#pragma unroll
    for (int o = 16; o; o >>= 1) s += __shfl_xor_sync(0xffffffffu, s, o);
    if ((tid & 31) == 0) red2[tid >> 5] = s;
    __syncthreads();
    if (tid < 32) {
        float v = (tid < 8) ? red2[tid] : 0.0f;
#pragma unroll
        for (int o = 4; o; o >>= 1) v += __shfl_xor_sync(0xffffffffu, v, o);
        red2[tid] = v;
    }
    __syncthreads();
    float inv = 1.0f / red2[0];
#pragma unroll
    for (int r = 0; r < 8; r++) p[tid + r * 256] = local[r] * inv;
}

extern "C" void kernel_launch(void* const* d_in, const int* in_sizes, int n_in,
                              void* d_out, int out_size)
{
    const float* x = (const float*)d_in[0];   // [4, 2048, 768]
    const float* w = (const float*)d_in[1];   // [3, 768, 768]
    float* out = (float*)d_out;               // [4, 2048, 768]

    float* qkv;
    float* s;
    cudaGetSymbolAddress((void**)&qkv, g_qkv);
    cudaGetSymbolAddress((void**)&s, g_s);

    const long QKV_PLANE = 8192L * 768;   // one of q/k/v, all batches
    const long BATCH_QKV = 2048L * 768;   // one batch within a plane
    const long BATCH_S   = 2048L * 2048;

    // 1) QKV: [8192,768] x [768,768] per weight slice s in {q,k,v}
    gemm_kernel<false><<<dim3(6, 64, 3), 256>>>(
        x, w, qkv,
        8192, 768, 768, 768, 768, 768,
        0L, 768L * 768, QKV_PLANE, 1.0f);

    // 2) scores = (Q K^T) / 8 per batch: [2048,768] x [2048,768]^T
    gemm_kernel<true><<<dim3(16, 16, 4), 256>>>(
        qkv /*Q*/, qkv + QKV_PLANE /*K*/, s,
        2048, 2048, 768, 768, 768, 2048,
        BATCH_QKV, BATCH_QKV, BATCH_S, 0.125f);

    // 3) softmax over rows (4*2048 rows of length 2048)
    softmax_kernel<<<8192, 256>>>(s);

    // 4) out = P V per batch: [2048,2048] x [2048,768]
    gemm_kernel<false><<<dim3(6, 16, 4), 256>>>(
        s, qkv + 2 * QKV_PLANE, out,
        2048, 768, 2048, 2048, 768, 768,
        BATCH_S, BATCH_QKV, BATCH_QKV, 1.0f);
}

// round 4
// speedup vs baseline: 3.3968x; 3.3968x over previous
#include <cuda_runtime.h>
#include <cuda_bf16.h>
#include <cstdint>

// ---------------- scratch (no allocations allowed) ----------------
__device__ __nv_bfloat16 g_xhi[8192L * 768], g_xlo[8192L * 768];
__device__ __nv_bfloat16 g_wthi[3L * 768 * 768], g_wtlo[3L * 768 * 768];   // w transposed: [s][OUT][D]
__device__ __nv_bfloat16 g_qhi[8192L * 768], g_qlo[8192L * 768];
__device__ __nv_bfloat16 g_khi[8192L * 768], g_klo[8192L * 768];
__device__ __nv_bfloat16 g_vthi[4L * 768 * 2048], g_vtlo[4L * 768 * 2048]; // V^T per batch: [768][2048]
__device__ float g_s[4L * 2048 * 2048];
__device__ __nv_bfloat16 g_phi[4L * 2048 * 2048], g_plo[4L * 2048 * 2048];

// ---------------- helpers ----------------
__device__ __forceinline__ uint32_t smem_u32(const void* p) {
    uint32_t a;
    asm("{ .reg .u64 t; cvta.to.shared.u64 t, %1; cvt.u32.u64 %0, t; }" : "=r"(a) : "l"(p));
    return a;
}

#define LDSM_X4(R, addr) \
    asm volatile("ldmatrix.sync.aligned.m8n8.x4.shared.b16 {%0,%1,%2,%3}, [%4];" \
        : "=r"((R)[0]), "=r"((R)[1]), "=r"((R)[2]), "=r"((R)[3]) : "r"(addr))

#define MMA16816(C, A, B0, B1) \
    asm volatile("mma.sync.aligned.m16n8k16.row.col.f32.bf16.bf16.f32 " \
        "{%0,%1,%2,%3}, {%4,%5,%6,%7}, {%8,%9}, {%0,%1,%2,%3};" \
        : "+f"((C)[0]), "+f"((C)[1]), "+f"((C)[2]), "+f"((C)[3]) \
        : "r"((A)[0]), "r"((A)[1]), "r"((A)[2]), "r"((A)[3]), "r"(B0), "r"(B1))

// ---------------- tiled HMMA GEMM ----------------
// D[m,n] = alpha * sum_k A[m,k]*B[n,k], both operands bf16 hi/lo split, K-major.
// EPI 0: fp32 C. EPI 1: hi/lo bf16 planes. EPI 2: V-transpose hi/lo planes.
#define TILE 128
#define BK 64
#define OFF_AHI 0
#define OFF_ALO (16 * 1024)
#define OFF_BHI (32 * 1024)
#define OFF_BLO (48 * 1024)
#define STAGE_BYTES (64 * 1024)
#define SMEM_TOTAL (2 * STAGE_BYTES)

__device__ __forceinline__ void load_tile_async(
    uint32_t s_base, const __nv_bfloat16* __restrict__ g, long row0, int ld, int k0, int tid)
{
    // 128 rows x 64 bf16 = 128 rows x 8 chunks of 16B, SW128 swizzle
#pragma unroll
    for (int rep = 0; rep < 4; ++rep) {
        int i = tid + rep * 256;
        int r = i >> 3, c = i & 7;
        uint32_t sp = s_base + (uint32_t)(r * 128) + ((uint32_t)(c ^ (r & 7)) * 16);
        const void* gp = g + (row0 + r) * (long)ld + k0 + c * 8;
        asm volatile("cp.async.cg.shared.global [%0], [%1], 16;" :: "r"(sp), "l"(gp) : "memory");
    }
}

template <int EPI>
__global__ void __launch_bounds__(256, 1) mma_gemm(
    const __nv_bfloat16* __restrict__ Ahi, const __nv_bfloat16* __restrict__ Alo,
    const __nv_bfloat16* __restrict__ Bhi, const __nv_bfloat16* __restrict__ Blo,
    int K, int lda, int ldb, long sA, long sB,
    float alpha, float* __restrict__ Cf, long sC, int ldc,
    __nv_bfloat16* __restrict__ Chi, __nv_bfloat16* __restrict__ Clo)
{
    extern __shared__ __align__(1024) char smem_raw[];
    const uint32_t sm = smem_u32(smem_raw);

    const int tid = threadIdx.x;
    const int wid = tid >> 5, lane = tid & 31;
    const int wm = wid & 1, wn = wid >> 1;          // warp grid 2 (M) x 4 (N)
    const long bm = (long)blockIdx.y * TILE;
    const long bn = (long)blockIdx.x * TILE;
    const int z = blockIdx.z;

    const __nv_bfloat16* pAh = Ahi + z * sA;
    const __nv_bfloat16* pAl = Alo + z * sA;
    const __nv_bfloat16* pBh = Bhi + z * sB;
    const __nv_bfloat16* pBl = Blo + z * sB;

    // ldmatrix per-lane geometry
    const int a_row = (lane & 7) + ((lane >> 3) & 1) * 8;  // row within 16-row tile
    const int a_kh  = lane >> 4;                           // k half (chunk +0/+1)
    const int b_row = (lane & 7) + ((lane >> 4) & 1) * 8;  // row within 16-row (2x n8) pair
    const int b_kh  = (lane >> 3) & 1;

    float c[4][4][4];
#pragma unroll
    for (int i = 0; i < 4; i++)
#pragma unroll
        for (int j = 0; j < 4; j++)
#pragma unroll
            for (int e = 0; e < 4; e++) c[i][j][e] = 0.0f;

    const int iters = K / BK;

    // prologue: stage 0
    load_tile_async(sm + OFF_AHI, pAh, bm, lda, 0, tid);
    load_tile_async(sm + OFF_ALO, pAl, bm, lda, 0, tid);
    load_tile_async(sm + OFF_BHI, pBh, bn, ldb, 0, tid);
    load_tile_async(sm + OFF_BLO, pBl, bn, ldb, 0, tid);
    asm volatile("cp.async.commit_group;" ::: "memory");

    for (int it = 0; it < iters; ++it) {
        const int p = it & 1;
        const uint32_t sb = sm + p * STAGE_BYTES;

        if (it + 1 < iters) {
            const uint32_t sq = sm + (p ^ 1) * STAGE_BYTES;
            const int k0 = (it + 1) * BK;
            load_tile_async(sq + OFF_AHI, pAh, bm, lda, k0, tid);
            load_tile_async(sq + OFF_ALO, pAl, bm, lda, k0, tid);
            load_tile_async(sq + OFF_BHI, pBh, bn, ldb, k0, tid);
            load_tile_async(sq + OFF_BLO, pBl, bn, ldb, k0, tid);
            asm volatile("cp.async.commit_group;" ::: "memory");
            asm volatile("cp.async.wait_group 1;" ::: "memory");
        } else {
            asm volatile("cp.async.wait_group 0;" ::: "memory");
        }
        __syncthreads();

#pragma unroll
        for (int ks = 0; ks < 4; ++ks) {
            uint32_t ah[4][4], al[4][4], bh[4][2], bl[4][2];
            // A fragments: 4 M-tiles x (hi,lo)
#pragma unroll
            for (int i = 0; i < 4; ++i) {
                int rg = wm * 64 + i * 16 + a_row;
                uint32_t off = (uint32_t)(rg * 128) +
                               ((uint32_t)((2 * ks + a_kh) ^ (rg & 7)) * 16);
                LDSM_X4(ah[i], sb + OFF_AHI + off);
                LDSM_X4(al[i], sb + OFF_ALO + off);
            }
            // B fragments: 2 x4-loads per plane -> 4 n8 tiles
#pragma unroll
            for (int j = 0; j < 2; ++j) {
                int rg = wn * 32 + j * 16 + b_row;
                uint32_t off = (uint32_t)(rg * 128) +
                               ((uint32_t)((2 * ks + b_kh) ^ (rg & 7)) * 16);
                uint32_t t[4];
                LDSM_X4(t, sb + OFF_BHI + off);
                bh[2 * j][0] = t[0]; bh[2 * j][1] = t[1];
                bh[2 * j + 1][0] = t[2]; bh[2 * j + 1][1] = t[3];
                LDSM_X4(t, sb + OFF_BLO + off);
                bl[2 * j][0] = t[0]; bl[2 * j][1] = t[1];
                bl[2 * j + 1][0] = t[2]; bl[2 * j + 1][1] = t[3];
            }
#pragma unroll
            for (int i = 0; i < 4; ++i)
#pragma unroll
                for (int j = 0; j < 4; ++j) {
                    MMA16816(c[i][j], ah[i], bh[j][0], bh[j][1]);
                    MMA16816(c[i][j], ah[i], bl[j][0], bl[j][1]);
                    MMA16816(c[i][j], al[i], bh[j][0], bh[j][1]);
                }
        }
        __syncthreads();
    }

    // ---------------- epilogue ----------------
    const int t4 = lane >> 2;
    const int t2 = (lane & 3) * 2;
#pragma unroll
    for (int i = 0; i < 4; ++i) {
        const long r0 = bm + wm * 64 + i * 16 + t4;
        const long r1 = r0 + 8;
#pragma unroll
        for (int j = 0; j < 4; ++j) {
            const long col = bn + wn * 32 + j * 8 + t2;
            if (EPI == 0) {
                float* base = Cf + z * sC;
                float2 v0 = make_float2(alpha * c[i][j][0], alpha * c[i][j][1]);
                float2 v1 = make_float2(alpha * c[i][j][2], alpha * c[i][j][3]);
                *reinterpret_cast<float2*>(base + r0 * ldc + col) = v0;
                *reinterpret_cast<float2*>(base + r1 * ldc + col) = v1;
            } else if (EPI == 1) {
#pragma unroll
                for (int h = 0; h < 2; ++h) {
                    const long r = h ? r1 : r0;
                    const float va = c[i][j][2 * h], vb = c[i][j][2 * h + 1];
                    __nv_bfloat16 ha = __float2bfloat16(va);
                    __nv_bfloat16 hb = __float2bfloat16(vb);
                    __nv_bfloat162 hv; hv.x = ha; hv.y = hb;
                    __nv_bfloat162 lv;
                    lv.x = __float2bfloat16(va - __bfloat162float(ha));
                    lv.y = __float2bfloat16(vb - __bfloat162float(hb));
                    *reinterpret_cast<__nv_bfloat162*>(Chi + r * ldc + col) = hv;
                    *reinterpret_cast<__nv_bfloat162*>(Clo + r * ldc + col) = lv;
                }
            } else {
                // V transpose: out [batch][768][2048], m = token row, n = feature col
#pragma unroll
                for (int h = 0; h < 2; ++h) {
                    const long m = h ? r1 : r0;
                    const long batch = m >> 11, mloc = m & 2047;
#pragma unroll
                    for (int e = 0; e < 2; ++e) {
                        const long n = col + e;
                        const float v = c[i][j][2 * h + e];
                        __nv_bfloat16 hh = __float2bfloat16(v);
                        const long o = (batch * 768 + n) * 2048 + mloc;
                        Chi[o] = hh;
                        Clo[o] = __float2bfloat16(v - __bfloat162float(hh));
                    }
                }
            }
        }
    }
}

// ---------------- splits / softmax ----------------
__global__ void split_kernel(const float* __restrict__ x,
                             __nv_bfloat16* __restrict__ hi, __nv_bfloat16* __restrict__ lo, long n)
{
    long i = (long)blockIdx.x * blockDim.x + threadIdx.x;
    if (i < n) {
        float f = x[i];
        __nv_bfloat16 h = __float2bfloat16(f);
        hi[i] = h;
        lo[i] = __float2bfloat16(f - __bfloat162float(h));
    }
}

__global__ void wsplit_kernel(const float* __restrict__ w,
                              __nv_bfloat16* __restrict__ hi, __nv_bfloat16* __restrict__ lo)
{
    // out[s][o][d] = w[s][d][o]
    long i = (long)blockIdx.x * blockDim.x + threadIdx.x;
    if (i < 3L * 768 * 768) {
        long s = i / (768 * 768), r = i % (768 * 768);
        long o = r / 768, d = r % 768;
        float f = w[s * 768 * 768 + d * 768 + o];
        __nv_bfloat16 h = __float2bfloat16(f);
        hi[i] = h;
        lo[i] = __float2bfloat16(f - __bfloat162float(h));
    }
}

__global__ __launch_bounds__(256) void softmax_kernel(
    const float* __restrict__ S, __nv_bfloat16* __restrict__ Phi, __nv_bfloat16* __restrict__ Plo)
{
    const long row = blockIdx.x;
    const float* p = S + row * 2048;
    const int tid = threadIdx.x;

    float local[8];
    float mx = -1e30f;
#pragma unroll
    for (int r = 0; r < 8; r++) { local[r] = p[tid + r * 256]; mx = fmaxf(mx, local[r]); }

    __shared__ float red[32];
#pragma unroll
    for (int o = 16; o; o >>= 1) mx = fmaxf(mx, __shfl_xor_sync(0xffffffffu, mx, o));
    if ((tid & 31) == 0) red[tid >> 5] = mx;
    __syncthreads();
    if (tid < 32) {
        float v = (tid < 8) ? red[tid] : -1e30f;
#pragma unroll
        for (int o = 4; o; o >>= 1) v = fmaxf(v, __shfl_xor_sync(0xffffffffu, v, o));
        red[tid] = v;
    }
    __syncthreads();
    mx = red[0];

    float s = 0.0f;
#pragma unroll
    for (int r = 0; r < 8; r++) { local[r] = __expf(local[r] - mx); s += local[r]; }
    __shared__ float red2[32];
#pragma unroll
    for (int o = 16; o; o >>= 1) s += __shfl_xor_sync(0xffffffffu, s, o);
    if ((tid & 31) == 0) red2[tid >> 5] = s;
    __syncthreads();
    if (tid < 32) {
        float v = (tid < 8) ? red2[tid] : 0.0f;
#pragma unroll
        for (int o = 4; o; o >>= 1) v += __shfl_xor_sync(0xffffffffu, v, o);
        red2[tid] = v;
    }
    __syncthreads();
    const float inv = 1.0f / red2[0];
#pragma unroll
    for (int r = 0; r < 8; r++) {
        float v = local[r] * inv;
        __nv_bfloat16 h = __float2bfloat16(v);
        long o = row * 2048 + tid + r * 256;
        Phi[o] = h;
        Plo[o] = __float2bfloat16(v - __bfloat162float(h));
    }
}

// ---------------- host ----------------
extern "C" void kernel_launch(void* const* d_in, const int* in_sizes, int n_in,
                              void* d_out, int out_size)
{
    const float* x = (const float*)d_in[0];   // [4,2048,768]
    const float* w = (const float*)d_in[1];   // [3,768,768]
    float* out = (float*)d_out;               // [4,2048,768]

    __nv_bfloat16 *xhi, *xlo, *wthi, *wtlo, *qhi, *qlo, *khi, *klo, *vthi, *vtlo, *phi, *plo;
    float* s;
    cudaGetSymbolAddress((void**)&xhi, g_xhi);   cudaGetSymbolAddress((void**)&xlo, g_xlo);
    cudaGetSymbolAddress((void**)&wthi, g_wthi); cudaGetSymbolAddress((void**)&wtlo, g_wtlo);
    cudaGetSymbolAddress((void**)&qhi, g_qhi);   cudaGetSymbolAddress((void**)&qlo, g_qlo);
    cudaGetSymbolAddress((void**)&khi, g_khi);   cudaGetSymbolAddress((void**)&klo, g_klo);
    cudaGetSymbolAddress((void**)&vthi, g_vthi); cudaGetSymbolAddress((void**)&vtlo, g_vtlo);
    cudaGetSymbolAddress((void**)&phi, g_phi);   cudaGetSymbolAddress((void**)&plo, g_plo);
    cudaGetSymbolAddress((void**)&s, g_s);

    cudaFuncSetAttribute(mma_gemm<0>, cudaFuncAttributeMaxDynamicSharedMemorySize, SMEM_TOTAL);
    cudaFuncSetAttribute(mma_gemm<1>, cudaFuncAttributeMaxDynamicSharedMemorySize, SMEM_TOTAL);
    cudaFuncSetAttribute(mma_gemm<2>, cudaFuncAttributeMaxDynamicSharedMemorySize, SMEM_TOTAL);

    // splits
    split_kernel<<<(8192L * 768 + 1023) / 1024, 1024>>>(x, xhi, xlo, 8192L * 768);
    wsplit_kernel<<<(3L * 768 * 768 + 1023) / 1024, 1024>>>(w, wthi, wtlo);

    const long WSL = 768L * 768;
    // QKV projections: M=8192, N=768, K=768
    mma_gemm<1><<<dim3(6, 64, 1), 256, SMEM_TOTAL>>>(
        xhi, xlo, wthi + 0 * WSL, wtlo + 0 * WSL, 768, 768, 768, 0L, 0L,
        1.0f, nullptr, 0L, 768, qhi, qlo);
    mma_gemm<1><<<dim3(6, 64, 1), 256, SMEM_TOTAL>>>(
        xhi, xlo, wthi + 1 * WSL, wtlo + 1 * WSL, 768, 768, 768, 0L, 0L,
        1.0f, nullptr, 0L, 768, khi, klo);
    mma_gemm<2><<<dim3(6, 64, 1), 256, SMEM_TOTAL>>>(
        xhi, xlo, wthi + 2 * WSL, wtlo + 2 * WSL, 768, 768, 768, 0L, 0L,
        1.0f, nullptr, 0L, 0, vthi, vtlo);

    // scores = Q K^T / 8 : per batch M=2048, N=2048, K=768
    mma_gemm<0><<<dim3(16, 16, 4), 256, SMEM_TOTAL>>>(
        qhi, qlo, khi, klo, 768, 768, 768, 2048L * 768, 2048L * 768,
        0.125f, s, 2048L * 2048, 2048, nullptr, nullptr);

    // softmax rows -> P hi/lo
    softmax_kernel<<<8192, 256>>>(s, phi, plo);

    // out = P V : per batch M=2048, N=768, K=2048 (B = V^T planes)
    mma_gemm<0><<<dim3(6, 16, 4), 256, SMEM_TOTAL>>>(
        phi, plo, vthi, vtlo, 2048, 2048, 2048, 2048L * 2048, 768L * 2048,
        1.0f, out, 2048L * 768, 768, nullptr, nullptr);
}

// round 5
// speedup vs baseline: 4.8975x; 1.4418x over previous
#include <cuda_runtime.h>
#include <cuda_fp16.h>
#include <cstdint>

// ---------------- scratch ----------------
__device__ __half g_xh[8192L * 768];
__device__ __half g_wth[3L * 768 * 768], g_wtl[3L * 768 * 768];  // W^T: [s][OUT][D] hi/lo
__device__ __half g_qh[8192L * 768];
__device__ __half g_kh[8192L * 768], g_kl[8192L * 768];
__device__ __half g_vth[4L * 768 * 2048], g_vtl[4L * 768 * 2048]; // V^T per batch: [768][2048]
__device__ float g_s[4L * 2048 * 2048];
__device__ __half g_ph[4L * 2048 * 2048];

// ---------------- helpers ----------------
__device__ __forceinline__ uint32_t smem_u32(const void* p) {
    uint32_t a;
    asm("{ .reg .u64 t; cvta.to.shared.u64 t, %1; cvt.u32.u64 %0, t; }" : "=r"(a) : "l"(p));
    return a;
}
#define LDSM_X4(R, addr) \
    asm volatile("ldmatrix.sync.aligned.m8n8.x4.shared.b16 {%0,%1,%2,%3}, [%4];" \
        : "=r"((R)[0]), "=r"((R)[1]), "=r"((R)[2]), "=r"((R)[3]) : "r"(addr))
#define MMA16816(C, A, B0, B1) \
    asm volatile("mma.sync.aligned.m16n8k16.row.col.f32.f16.f16.f32 " \
        "{%0,%1,%2,%3}, {%4,%5,%6,%7}, {%8,%9}, {%0,%1,%2,%3};" \
        : "+f"((C)[0]), "+f"((C)[1]), "+f"((C)[2]), "+f"((C)[3]) \
        : "r"((A)[0]), "r"((A)[1]), "r"((A)[2]), "r"((A)[3]), "r"(B0), "r"(B1))

// ---------------- tiling ----------------
#define TILE 128
#define BK 64
#define STAGES 4
#define OFF_A 0
#define OFF_BH (16 * 1024)
#define OFF_BL (32 * 1024)
#define STAGE_BYTES (48 * 1024)
#define SMEM_TOTAL (STAGES * STAGE_BYTES)

__device__ __forceinline__ void load_tile_async(
    uint32_t s_base, const __half* __restrict__ g, long row0, int ld, int k0, int tid)
{
    // 128 rows x 64 halves (128B/row), SW128 swizzle, 16B chunks
#pragma unroll
    for (int rep = 0; rep < 4; ++rep) {
        int i = tid + rep * 256;
        int r = i >> 3, c = i & 7;
        uint32_t sp = s_base + (uint32_t)(r * 128) + ((uint32_t)(c ^ (r & 7)) * 16);
        const void* gp = g + (row0 + r) * (long)ld + k0 + c * 8;
        asm volatile("cp.async.cg.shared.global [%0], [%1], 16;" :: "r"(sp), "l"(gp) : "memory");
    }
}

// D[m,n] += A_hi[m,k]*(B_hi[n,k]+B_lo[n,k]), K-major operands, 128x128 tile.
__device__ __forceinline__ void gemm_mainloop(
    uint32_t sm, const __half* __restrict__ pA,
    const __half* __restrict__ pBh, const __half* __restrict__ pBl,
    int K, int lda, int ldb, long bm, long bn, int tid, float (&c)[4][4][4])
{
    const int lane = tid & 31, wid = tid >> 5;
    const int wm = wid & 1, wn = wid >> 1;

    const int a_row = (lane & 7) + ((lane >> 3) & 1) * 8;
    const int a_kh  = lane >> 4;
    const int b_row = (lane & 7) + ((lane >> 4) & 1) * 8;
    const int b_kh  = (lane >> 3) & 1;

    const int iters = K / BK;

    // prologue: stages 0..STAGES-2
#pragma unroll
    for (int s = 0; s < STAGES - 1; ++s) {
        if (s < iters) {
            const uint32_t sb = sm + s * STAGE_BYTES;
            load_tile_async(sb + OFF_A, pA, bm, lda, s * BK, tid);
            load_tile_async(sb + OFF_BH, pBh, bn, ldb, s * BK, tid);
            load_tile_async(sb + OFF_BL, pBl, bn, ldb, s * BK, tid);
        }
        asm volatile("cp.async.commit_group;" ::: "memory");
    }

    for (int it = 0; it < iters; ++it) {
        asm volatile("cp.async.wait_group %0;" :: "n"(STAGES - 2) : "memory");
        __syncthreads();

        {
            const int ld_it = it + STAGES - 1;
            if (ld_it < iters) {
                const uint32_t sq = sm + (ld_it % STAGES) * STAGE_BYTES;
                load_tile_async(sq + OFF_A, pA, bm, lda, ld_it * BK, tid);
                load_tile_async(sq + OFF_BH, pBh, bn, ldb, ld_it * BK, tid);
                load_tile_async(sq + OFF_BL, pBl, bn, ldb, ld_it * BK, tid);
            }
            asm volatile("cp.async.commit_group;" ::: "memory");
        }

        const uint32_t sb = sm + (it % STAGES) * STAGE_BYTES;
#pragma unroll
        for (int ks = 0; ks < 4; ++ks) {
            uint32_t ah[4][4], bh[4][2], bl[4][2];
#pragma unroll
            for (int i = 0; i < 4; ++i) {
                int rg = wm * 64 + i * 16 + a_row;
                uint32_t off = (uint32_t)(rg * 128) +
                               ((uint32_t)((2 * ks + a_kh) ^ (rg & 7)) * 16);
                LDSM_X4(ah[i], sb + OFF_A + off);
            }
#pragma unroll
            for (int j = 0; j < 2; ++j) {
                int rg = wn * 32 + j * 16 + b_row;
                uint32_t off = (uint32_t)(rg * 128) +
                               ((uint32_t)((2 * ks + b_kh) ^ (rg & 7)) * 16);
                uint32_t t[4];
                LDSM_X4(t, sb + OFF_BH + off);
                bh[2 * j][0] = t[0]; bh[2 * j][1] = t[1];
                bh[2 * j + 1][0] = t[2]; bh[2 * j + 1][1] = t[3];
                LDSM_X4(t, sb + OFF_BL + off);
                bl[2 * j][0] = t[0]; bl[2 * j][1] = t[1];
                bl[2 * j + 1][0] = t[2]; bl[2 * j + 1][1] = t[3];
            }
#pragma unroll
            for (int i = 0; i < 4; ++i)
#pragma unroll
                for (int j = 0; j < 4; ++j) {
                    MMA16816(c[i][j], ah[i], bh[j][0], bh[j][1]);
                    MMA16816(c[i][j], ah[i], bl[j][0], bl[j][1]);
                }
        }
    }
}

// ---------------- QKV kernel (merged, z selects output) ----------------
__global__ void __launch_bounds__(256, 1) qkv_gemm(
    const __half* __restrict__ xh,
    const __half* __restrict__ wth, const __half* __restrict__ wtl,
    __half* __restrict__ qh,
    __half* __restrict__ kh, __half* __restrict__ kl,
    __half* __restrict__ vth, __half* __restrict__ vtl)
{
    extern __shared__ __align__(1024) char smem_raw[];
    const uint32_t sm = smem_u32(smem_raw);
    const int tid = threadIdx.x;
    const int lane = tid & 31, wid = tid >> 5;
    const int wm = wid & 1, wn = wid >> 1;
    const long bm = (long)blockIdx.y * TILE;
    const long bn = (long)blockIdx.x * TILE;
    const int z = blockIdx.z;
    const long WSL = 768L * 768;

    float c[4][4][4];
#pragma unroll
    for (int i = 0; i < 4; i++)
#pragma unroll
        for (int j = 0; j < 4; j++)
#pragma unroll
            for (int e = 0; e < 4; e++) c[i][j][e] = 0.0f;

    gemm_mainloop(sm, xh, wth + z * WSL, wtl + z * WSL, 768, 768, 768, bm, bn, tid, c);

    const int t4 = lane >> 2;
    const int t2 = (lane & 3) * 2;

    if (z < 2) {
        __half* hp = (z == 0) ? qh : kh;
#pragma unroll
        for (int i = 0; i < 4; ++i) {
            const long r0 = bm + wm * 64 + i * 16 + t4;
#pragma unroll
            for (int j = 0; j < 4; ++j) {
                const long col = bn + wn * 32 + j * 8 + t2;
#pragma unroll
                for (int h = 0; h < 2; ++h) {
                    const long r = r0 + 8 * h;
                    const float va = c[i][j][2 * h], vb = c[i][j][2 * h + 1];
                    const __half ha = __float2half(va), hb = __float2half(vb);
                    *reinterpret_cast<__half2*>(hp + r * 768 + col) = __halves2half2(ha, hb);
                    if (z == 1) {
                        __half2 lv = __halves2half2(
                            __float2half(va - __half2float(ha)),
                            __float2half(vb - __half2float(hb)));
                        *reinterpret_cast<__half2*>(kl + r * 768 + col) = lv;
                    }
                }
            }
        }
    } else {
        // V^T: transpose through smem, then coalesced stores to [batch][768][2048]
        float* smemT = reinterpret_cast<float*>(smem_raw);  // [128 cols][132 pad]
        __syncthreads();  // all warps done reading stages
#pragma unroll
        for (int i = 0; i < 4; ++i) {
            const int rl0 = wm * 64 + i * 16 + t4;
#pragma unroll
            for (int j = 0; j < 4; ++j) {
                const int cl = wn * 32 + j * 8 + t2;
#pragma unroll
                for (int h = 0; h < 2; ++h) {
                    smemT[(cl + 0) * 132 + rl0 + 8 * h] = c[i][j][2 * h + 0];
                    smemT[(cl + 1) * 132 + rl0 + 8 * h] = c[i][j][2 * h + 1];
                }
            }
        }
        __syncthreads();
        const long batch = bm >> 11, mbase = bm & 2047;
#pragma unroll
        for (int idx = tid; idx < 128 * 32; idx += 256) {
            const int nl = idx >> 5, m4 = (idx & 31) * 4;
            float4 v = *reinterpret_cast<float4*>(&smemT[nl * 132 + m4]);
            const long o = (batch * 768 + bn + nl) * 2048 + mbase + m4;
            __half h0 = __float2half(v.x), h1 = __float2half(v.y);
            __half h2 = __float2half(v.z), h3 = __float2half(v.w);
            *reinterpret_cast<__half2*>(vth + o)     = __halves2half2(h0, h1);
            *reinterpret_cast<__half2*>(vth + o + 2) = __halves2half2(h2, h3);
            __half l0 = __float2half(v.x - __half2float(h0));
            __half l1 = __float2half(v.y - __half2float(h1));
            __half l2 = __float2half(v.z - __half2float(h2));
            __half l3 = __float2half(v.w - __half2float(h3));
            *reinterpret_cast<__half2*>(vtl + o)     = __halves2half2(l0, l1);
            *reinterpret_cast<__half2*>(vtl + o + 2) = __halves2half2(l2, l3);
        }
    }
}

// ---------------- generic fp32-out GEMM (scores, PV) ----------------
__global__ void __launch_bounds__(256, 1) gemm_f32out(
    const __half* __restrict__ A,
    const __half* __restrict__ Bh, const __half* __restrict__ Bl,
    int K, int lda, int ldb, long sA, long sB,
    float alpha, float* __restrict__ C, long sC, int ldc)
{
    extern __shared__ __align__(1024) char smem_raw[];
    const uint32_t sm = smem_u32(smem_raw);
    const int tid = threadIdx.x;
    const int lane = tid & 31, wid = tid >> 5;
    const int wm = wid & 1, wn = wid >> 1;
    const long bm = (long)blockIdx.y * TILE;
    const long bn = (long)blockIdx.x * TILE;
    const int z = blockIdx.z;

    float c[4][4][4];
#pragma unroll
    for (int i = 0; i < 4; i++)
#pragma unroll
        for (int j = 0; j < 4; j++)
#pragma unroll
            for (int e = 0; e < 4; e++) c[i][j][e] = 0.0f;

    gemm_mainloop(sm, A + z * sA, Bh + z * sB, Bl + z * sB, K, lda, ldb, bm, bn, tid, c);

    const int t4 = lane >> 2;
    const int t2 = (lane & 3) * 2;
    float* base = C + z * sC;
#pragma unroll
    for (int i = 0; i < 4; ++i) {
        const long r0 = bm + wm * 64 + i * 16 + t4;
        const long r1 = r0 + 8;
#pragma unroll
        for (int j = 0; j < 4; ++j) {
            const long col = bn + wn * 32 + j * 8 + t2;
            *reinterpret_cast<float2*>(base + r0 * ldc + col) =
                make_float2(alpha * c[i][j][0], alpha * c[i][j][1]);
            *reinterpret_cast<float2*>(base + r1 * ldc + col) =
                make_float2(alpha * c[i][j][2], alpha * c[i][j][3]);
        }
    }
}

// ---------------- splits / softmax ----------------
__global__ void split_x_kernel(const float* __restrict__ x, __half* __restrict__ xh, long n)
{
    long i = (long)blockIdx.x * blockDim.x + threadIdx.x;
    if (i < n) xh[i] = __float2half(x[i]);
}

__global__ void wsplit_kernel(const float* __restrict__ w,
                              __half* __restrict__ hi, __half* __restrict__ lo)
{
    // out[s][o][d] = w[s][d][o]
    long i = (long)blockIdx.x * blockDim.x + threadIdx.x;
    if (i < 3L * 768 * 768) {
        long s = i / (768 * 768), r = i % (768 * 768);
        long o = r / 768, d = r % 768;
        float f = w[s * 768 * 768 + d * 768 + o];
        __half h = __float2half(f);
        hi[i] = h;
        lo[i] = __float2half(f - __half2float(h));
    }
}

__global__ __launch_bounds__(256) void softmax_kernel(
    const float* __restrict__ S, __half* __restrict__ Ph)
{
    const long row = blockIdx.x;
    const float* p = S + row * 2048;
    const int tid = threadIdx.x;

    float local[8];
    float mx = -1e30f;
#pragma unroll
    for (int r = 0; r < 8; r++) { local[r] = p[tid + r * 256]; mx = fmaxf(mx, local[r]); }

    __shared__ float red[32];
#pragma unroll
    for (int o = 16; o; o >>= 1) mx = fmaxf(mx, __shfl_xor_sync(0xffffffffu, mx, o));
    if ((tid & 31) == 0) red[tid >> 5] = mx;
    __syncthreads();
    if (tid < 32) {
        float v = (tid < 8) ? red[tid] : -1e30f;
#pragma unroll
        for (int o = 4; o; o >>= 1) v = fmaxf(v, __shfl_xor_sync(0xffffffffu, v, o));
        red[tid] = v;
    }
    __syncthreads();
    mx = red[0];

    float s = 0.0f;
#pragma unroll
    for (int r = 0; r < 8; r++) { local[r] = __expf(local[r] - mx); s += local[r]; }
    __shared__ float red2[32];
#pragma unroll
    for (int o = 16; o; o >>= 1) s += __shfl_xor_sync(0xffffffffu, s, o);
    if ((tid & 31) == 0) red2[tid >> 5] = s;
    __syncthreads();
    if (tid < 32) {
        float v = (tid < 8) ? red2[tid] : 0.0f;
#pragma unroll
        for (int o = 4; o; o >>= 1) v += __shfl_xor_sync(0xffffffffu, v, o);
        red2[tid] = v;
    }
    __syncthreads();
    const float inv = 1.0f / red2[0];
#pragma unroll
    for (int r = 0; r < 8; r++)
        Ph[row * 2048 + tid + r * 256] = __float2half(local[r] * inv);
}

// ---------------- host ----------------
extern "C" void kernel_launch(void* const* d_in, const int* in_sizes, int n_in,
                              void* d_out, int out_size)
{
    const float* x = (const float*)d_in[0];   // [4,2048,768]
    const float* w = (const float*)d_in[1];   // [3,768,768]
    float* out = (float*)d_out;               // [4,2048,768]

    __half *xh, *wth, *wtl, *qh, *kh, *kl, *vth, *vtl, *ph;
    float* s;
    cudaGetSymbolAddress((void**)&xh, g_xh);
    cudaGetSymbolAddress((void**)&wth, g_wth); cudaGetSymbolAddress((void**)&wtl, g_wtl);
    cudaGetSymbolAddress((void**)&qh, g_qh);
    cudaGetSymbolAddress((void**)&kh, g_kh);   cudaGetSymbolAddress((void**)&kl, g_kl);
    cudaGetSymbolAddress((void**)&vth, g_vth); cudaGetSymbolAddress((void**)&vtl, g_vtl);
    cudaGetSymbolAddress((void**)&ph, g_ph);
    cudaGetSymbolAddress((void**)&s, g_s);

    cudaFuncSetAttribute(qkv_gemm, cudaFuncAttributeMaxDynamicSharedMemorySize, SMEM_TOTAL);
    cudaFuncSetAttribute(gemm_f32out, cudaFuncAttributeMaxDynamicSharedMemorySize, SMEM_TOTAL);

    split_x_kernel<<<(8192L * 768 + 1023) / 1024, 1024>>>(x, xh, 8192L * 768);
    wsplit_kernel<<<(3L * 768 * 768 + 1023) / 1024, 1024>>>(w, wth, wtl);

    // QKV: M=8192, N=768, K=768, z = {Q, K, V}
    qkv_gemm<<<dim3(6, 64, 3), 256, SMEM_TOTAL>>>(xh, wth, wtl, qh, kh, kl, vth, vtl);

    // scores = Q K^T / 8 : per batch M=2048, N=2048, K=768
    gemm_f32out<<<dim3(16, 16, 4), 256, SMEM_TOTAL>>>(
        qh, kh, kl, 768, 768, 768, 2048L * 768, 2048L * 768,
        0.125f, s, 2048L * 2048, 2048);

    // softmax rows -> P hi
    softmax_kernel<<<8192, 256>>>(s, ph);

    // out = P V : per batch M=2048, N=768, K=2048 (B = V^T hi/lo)
    gemm_f32out<<<dim3(6, 16, 4), 256, SMEM_TOTAL>>>(
        ph, vth, vtl, 2048, 2048, 2048, 2048L * 2048, 768L * 2048,
        1.0f, out, 2048L * 768, 768);
}